// round 16
// baseline (speedup 1.0000x reference)
#include <cuda_runtime.h>
#include <cuda_fp16.h>
#include <cstdint>
#include <cstddef>

// ---------------- problem constants ----------------
#define EXPERTS 8
#define HDIM    2048
#define FDIM    8192
#define TOKENS  16384
#define CAP     2048

// fp16 staging buffers (static __device__ memory: allocation-guard safe)
__device__ __half g_xh [(size_t)TOKENS  * HDIM];          //  64 MB
__device__ __half g_w1h[(size_t)EXPERTS * HDIM * FDIM];   // 256 MB
__device__ __half g_w2h[(size_t)EXPERTS * FDIM * HDIM];   // 256 MB
__device__ __half g_hidh[(size_t)TOKENS * FDIM];          // 256 MB

// ---------------- fp32 -> fp16 (RN) bulk convert (x + first half of w1) ----------------
// Blocks [0, XB) handle x; blocks [XB, XB+WB) handle w1[experts 0..3].
static constexpr int CVT_XB = 512;    // x: 8M float4 -> 16384/blk
static constexpr int CVT_WB = 2048;   // w1 half: 16.78M float4 -> 8192/blk
__global__ void cvt_xw1h(const float* __restrict__ xs, __half* __restrict__ xd,
                         const float* __restrict__ ws, __half* __restrict__ wd) {
    const float4* s4; __half2* d2; size_t i, end;
    if (blockIdx.x < CVT_XB) {
        const size_t per = ((size_t)TOKENS * HDIM / 4) / CVT_XB;
        s4 = (const float4*)xs; d2 = (__half2*)xd;
        i = (size_t)blockIdx.x * per + threadIdx.x; end = (size_t)(blockIdx.x + 1) * per;
    } else {
        const size_t per = ((size_t)(EXPERTS / 2) * HDIM * FDIM / 4) / CVT_WB;
        s4 = (const float4*)ws; d2 = (__half2*)wd;
        i = (size_t)(blockIdx.x - CVT_XB) * per + threadIdx.x;
        end = (size_t)(blockIdx.x - CVT_XB + 1) * per;
    }
    for (; i < end; i += blockDim.x) {
        float4 v = s4[i];
        d2[2 * i]     = __floats2half2_rn(v.x, v.y);
        d2[2 * i + 1] = __floats2half2_rn(v.z, v.w);
    }
}

// ---------------- PTX helpers ----------------
__device__ __forceinline__ uint32_t smem_u32(const void* p) {
    uint32_t a;
    asm("{ .reg .u64 t; cvta.to.shared.u64 t, %1; cvt.u32.u64 %0, t; }" : "=r"(a) : "l"(p));
    return a;
}
__device__ __forceinline__ void cpa16(uint32_t dst, const void* src) {
    asm volatile("cp.async.cg.shared.global [%0], [%1], 16;" :: "r"(dst), "l"(src));
}
#define CP_COMMIT() asm volatile("cp.async.commit_group;" ::: "memory")
#define CP_WAIT3()  asm volatile("cp.async.wait_group 3;"  ::: "memory")

__device__ __forceinline__ void ldsm_x4(uint32_t* r, uint32_t a) {
    asm volatile("ldmatrix.sync.aligned.m8n8.x4.shared.b16 {%0,%1,%2,%3}, [%4];"
                 : "=r"(r[0]), "=r"(r[1]), "=r"(r[2]), "=r"(r[3]) : "r"(a));
}
__device__ __forceinline__ void ldsm_x4t(uint32_t* r, uint32_t a) {
    asm volatile("ldmatrix.sync.aligned.m8n8.x4.trans.shared.b16 {%0,%1,%2,%3}, [%4];"
                 : "=r"(r[0]), "=r"(r[1]), "=r"(r[2]), "=r"(r[3]) : "r"(a));
}
__device__ __forceinline__ void mma16816(float* c, const uint32_t* a, const uint32_t* b) {
    asm volatile(
        "mma.sync.aligned.m16n8k16.row.col.f32.f16.f16.f32 "
        "{%0,%1,%2,%3}, {%4,%5,%6,%7}, {%8,%9}, {%0,%1,%2,%3};"
        : "+f"(c[0]), "+f"(c[1]), "+f"(c[2]), "+f"(c[3])
        : "r"(a[0]), "r"(a[1]), "r"(a[2]), "r"(a[3]), "r"(b[0]), "r"(b[1]));
}

// HW tanh (sm_75+): single MUFU op instead of the ~12-op library tanhf chain.
__device__ __forceinline__ float tanh_fast(float x) {
    float r; asm("tanh.approx.f32 %0, %1;" : "=f"(r) : "f"(x)); return r;
}
__device__ __forceinline__ float gelu_tanh(float x) {
    float x3 = x * x * x;
    float t  = tanh_fast(0.7978845608028654f * (x + 0.044715f * x3));
    return 0.5f * x * (1.0f + t);
}

// ---------------- SMEM layout ----------------
// BM=128, BN=128, BK=32, 6-stage ring (preload 4, prefetch distance 4).
// A stage: 128 rows x 64B padded to 80B pitch  (5 x 16B, gcd(5,8)=1)  -> 10240 B
// B stage:  32 k-rows x 256B padded to 272B   (17 x 16B, gcd(17,8)=1) ->  8704 B
// 6 stages: 113664 B/CTA; 2 CTAs = 222 KB <= 228 KB SM capacity -> 2 CTAs/SM.
static constexpr int A_PITCH   = 80;
static constexpr int B_PITCH   = 272;
static constexpr int A_STAGE   = 128 * A_PITCH;         // 10240
static constexpr int B_STAGE   = 32 * B_PITCH;          //  8704
static constexpr int NSTAGE    = 6;
static constexpr int B_OFF     = NSTAGE * A_STAGE;      // 61440
static constexpr int SMEM_SIZE = B_OFF + NSTAGE * B_STAGE;  // 113664

static constexpr int NX_GEMM      = FDIM / 128;          // 64 n-tiles for fc1
static constexpr int CVT_PER_BLK  = 32768;               // float4 per embedded cvt block

// ---------------- grouped GEMM: OUT[e] = act(A[e] @ W[e] + bias[e]) ----------------
// CTA 128x128 with 128 threads: 4 warps in 2x2, warp tile 64x64 (R7 shape).
// FC1 launches carry nx_cvt extra x-columns of blocks converting a disjoint
// fp32->fp16 chunk (w1 second half under fc1-half-1; w2 under fc1-half-2),
// interleaved through the CTA issue order. Kernel boundaries give ordering.
template <bool FC1>
__global__ void __launch_bounds__(128, 2)
moe_gemm(const float* __restrict__ bias, float* __restrict__ out, int K, int N,
         const float* __restrict__ cvtS, __half* __restrict__ cvtD,
         int nx_cvt, int zbase, int zdim)
{
    extern __shared__ char smem[];
    const uint32_t sb = smem_u32(smem);
    const int tid  = threadIdx.x;

    if (FC1 && blockIdx.x >= NX_GEMM) {
        // ---- embedded conversion block (disjoint CVT_PER_BLK float4 chunk) ----
        const int c = (blockIdx.x - NX_GEMM)
                    + nx_cvt * (blockIdx.y + (CAP / 128) * blockIdx.z);
        const float4* s4 = (const float4*)cvtS;
        __half2*      d2 = (__half2*)cvtD;
        const size_t base = (size_t)c * CVT_PER_BLK;
        for (int j = tid; j < CVT_PER_BLK; j += 128) {
            const size_t i = base + j;
            float4 v = s4[i];
            d2[2 * i]     = __floats2half2_rn(v.x, v.y);
            d2[2 * i + 1] = __floats2half2_rn(v.z, v.w);
        }
        return;
    }

    const int wid  = tid >> 5;
    const int lane = tid & 31;

    const int e  = zbase + blockIdx.z;
    const int m0 = blockIdx.y * 128;
    const int n0 = blockIdx.x * 128;

    const __half* A = (FC1 ? g_xh  : g_hidh) + ((size_t)(e * CAP + m0)) * (size_t)K;
    const __half* W = (FC1 ? g_w1h : g_w2h) + (size_t)e * K * N + n0;

    const int wm = (wid & 1) * 64;   // warp row offset
    const int wn = (wid >> 1) * 64;  // warp col offset

    // producer mapping (128 threads): A tile 512 segs (4/row), B tile 512 segs
    // (16/row); 4 each per thread.
    auto load_stage = [&](int stage, int kc) {
        uint32_t aS = sb + stage * A_STAGE;
        uint32_t bS = sb + B_OFF + stage * B_STAGE;
        #pragma unroll
        for (int j = 0; j < 4; ++j) {
            const int idx = tid + 128 * j;
            const int row = idx >> 2, seg = idx & 3;
            cpa16(aS + row * A_PITCH + seg * 16,
                  A + (size_t)row * K + kc + seg * 8);
        }
        #pragma unroll
        for (int j = 0; j < 4; ++j) {
            const int idx = tid + 128 * j;
            const int r = idx >> 4, seg = idx & 15;
            cpa16(bS + r * B_PITCH + seg * 16,
                  W + (size_t)(kc + r) * N + seg * 8);
        }
    };

    const int nk = K / 32;
    load_stage(0, 0);  CP_COMMIT();
    load_stage(1, 32); CP_COMMIT();
    load_stage(2, 64); CP_COMMIT();
    load_stage(3, 96); CP_COMMIT();

    float acc[4][8][4];
    #pragma unroll
    for (int i = 0; i < 4; ++i)
        #pragma unroll
        for (int j = 0; j < 8; ++j)
            #pragma unroll
            for (int q = 0; q < 4; ++q) acc[i][j][q] = 0.f;

    const int gid = lane >> 2, tig = lane & 3;
    // A ldmatrix (x4, non-trans)
    const uint32_t a_row  = lane & 15;
    const uint32_t a_koff = (lane >> 4) * 16;
    // B ldmatrix (x4, trans): mats 0,1 -> k 0-7/8-15; mats 2,3 -> +8 cols
    const int bmat  = lane >> 3;
    const int bt_k  = (bmat & 1) * 8 + (lane & 7);
    const int bt_n  = (bmat >> 1) * 8;

    // Hoisted per-warp-invariant LDSM address components.
    uint32_t aOff[4], bOff[4];
    #pragma unroll
    for (int mt = 0; mt < 4; ++mt)
        aOff[mt] = (uint32_t)((wm + mt * 16 + a_row) * A_PITCH) + a_koff;
    #pragma unroll
    for (int nh = 0; nh < 4; ++nh)
        bOff[nh] = (uint32_t)(bt_k * B_PITCH + (wn + nh * 16 + bt_n) * 2);

    // Modulo-free ring cursors: consume slot sc, prefetch slot sp.
    int sc = 0, sp = 4;

    for (int it = 0; it < nk; ++it) {
        // Early prefetch (distance 4): slot (it+4)%6 was last consumed at
        // iter it-2, retired by the barrier of iter it-1 -> race-free.
        const int pre = it + 4;
        if (pre < nk) {
            load_stage(sp, pre * 32); CP_COMMIT();
            if (++sp == NSTAGE) sp = 0;
        }

        CP_WAIT3();               // stage `it` complete
        __syncthreads();

        const uint32_t aS = sb + sc * A_STAGE;
        const uint32_t bS = sb + B_OFF + sc * B_STAGE;
        if (++sc == NSTAGE) sc = 0;

        #pragma unroll
        for (int ks = 0; ks < 2; ++ks) {             // two k=16 steps per BK=32
            uint32_t a[4][4], b[4][4];
            #pragma unroll
            for (int mt = 0; mt < 4; ++mt)
                ldsm_x4(a[mt], aS + aOff[mt] + ks * 32);
            #pragma unroll
            for (int nh = 0; nh < 4; ++nh)            // each yields two n8 blocks
                ldsm_x4t(b[nh], bS + bOff[nh] + ks * (16 * B_PITCH));
            #pragma unroll
            for (int mt = 0; mt < 4; ++mt)
                #pragma unroll
                for (int nt = 0; nt < 8; ++nt)
                    mma16816(acc[mt][nt], a[mt], &b[nt >> 1][(nt & 1) * 2]);
        }
    }

    // ---------------- epilogue ----------------
    const float* Bb = bias + (size_t)e * N + n0;
    #pragma unroll
    for (int mt = 0; mt < 4; ++mt) {
        const int r0 = wm + mt * 16 + gid;           // rows r0 and r0+8
        #pragma unroll
        for (int nt = 0; nt < 8; ++nt) {
            const int cl = wn + nt * 8 + 2 * tig;    // cols cl, cl+1
            const float bx = Bb[cl], by = Bb[cl + 1];
            float v00 = acc[mt][nt][0] + bx, v01 = acc[mt][nt][1] + by;
            float v10 = acc[mt][nt][2] + bx, v11 = acc[mt][nt][3] + by;
            size_t base0 = ((size_t)(e * CAP + m0 + r0)) * (size_t)N + n0 + cl;
            if (FC1) {
                v00 = gelu_tanh(v00); v01 = gelu_tanh(v01);
                v10 = gelu_tanh(v10); v11 = gelu_tanh(v11);
                *(__half2*)(g_hidh + base0)                 = __floats2half2_rn(v00, v01);
                *(__half2*)(g_hidh + base0 + (size_t)8 * N) = __floats2half2_rn(v10, v11);
            } else {
                *(float2*)(out + base0)                 = make_float2(v00, v01);
                *(float2*)(out + base0 + (size_t)8 * N) = make_float2(v10, v11);
            }
        }
    }
}

// ---------------- launch (single stream, kernel-boundary ordering only) ----------------
extern "C" void kernel_launch(void* const* d_in, const int* in_sizes, int n_in,
                              void* d_out, int out_size)
{
    const float* x  = (const float*)d_in[0];
    // d_in[1] = tokens_per_expert (equal capacity; unused)
    const float* w1 = (const float*)d_in[2];
    const float* b1 = (const float*)d_in[3];
    const float* w2 = (const float*)d_in[4];
    const float* b2 = (const float*)d_in[5];
    float* out = (float*)d_out;

    cudaFuncSetAttribute(moe_gemm<true>,
                         cudaFuncAttributeMaxDynamicSharedMemorySize, SMEM_SIZE);
    cudaFuncSetAttribute(moe_gemm<false>,
                         cudaFuncAttributeMaxDynamicSharedMemorySize, SMEM_SIZE);

    __half* xh;  cudaGetSymbolAddress((void**)&xh,  g_xh);
    __half* w1h; cudaGetSymbolAddress((void**)&w1h, g_w1h);
    __half* w2h; cudaGetSymbolAddress((void**)&w2h, g_w2h);

    const size_t w1_half_elems = (size_t)(EXPERTS / 2) * HDIM * FDIM;  // 67.1M

    // 1) staging: x (all) + w1 experts 0..3.
    cvt_xw1h<<<CVT_XB + CVT_WB, 256>>>(x, xh, w1, w1h);

    // 2) fc1 experts 0..3; embedded blocks (8 x-columns -> 512 blocks x 32768
    //    float4 = 16.78M) convert w1 experts 4..7 under the GEMM.
    moe_gemm<true><<<dim3(NX_GEMM + 8, CAP / 128, EXPERTS / 2), 128, SMEM_SIZE>>>(
        b1, nullptr, HDIM, FDIM,
        w1 + w1_half_elems, w1h + w1_half_elems, 8, 0, EXPERTS / 2);

    // 3) fc1 experts 4..7; embedded blocks (16 x-columns -> 1024 blocks x 32768
    //    float4 = 33.55M) convert all of w2 under the GEMM.
    moe_gemm<true><<<dim3(NX_GEMM + 16, CAP / 128, EXPERTS / 2), 128, SMEM_SIZE>>>(
        b1, nullptr, HDIM, FDIM,
        w2, w2h, 16, EXPERTS / 2, EXPERTS / 2);

    // 4) fc2 -> out (fp32); w2h complete by kernel-boundary order.
    moe_gemm<false><<<dim3(HDIM / 128, CAP / 128, EXPERTS), 128, SMEM_SIZE>>>(
        b2, out, FDIM, HDIM, nullptr, nullptr, 0, 0, EXPERTS);
}

// round 17
// speedup vs baseline: 1.0520x; 1.0520x over previous
#include <cuda_runtime.h>
#include <cuda_fp16.h>
#include <cstdint>
#include <cstddef>

// ---------------- problem constants ----------------
#define EXPERTS 8
#define HDIM    2048
#define FDIM    8192
#define TOKENS  16384
#define CAP     2048

// fp16 staging buffers (static __device__ memory: allocation-guard safe)
__device__ __half g_xh [(size_t)TOKENS  * HDIM];          //  64 MB
__device__ __half g_w1h[(size_t)EXPERTS * HDIM * FDIM];   // 256 MB
__device__ __half g_w2h[(size_t)EXPERTS * FDIM * HDIM];   // 256 MB
__device__ __half g_hidh[(size_t)TOKENS * FDIM];          // 256 MB

// ---------------- fp32 -> fp16 (RN) bulk convert (x and w1 in one launch) ----------------
// Blocks [0, XB) handle x; blocks [XB, XB+WB) handle w1.
static constexpr int CVT_XB = 512;    // x: 8M float4 -> 16384/blk
static constexpr int CVT_WB = 4096;   // w1: 32M float4 -> 8192/blk
__global__ void cvt_xw1(const float* __restrict__ xs, __half* __restrict__ xd,
                        const float* __restrict__ ws, __half* __restrict__ wd) {
    const float4* s4; __half2* d2; size_t i, end;
    if (blockIdx.x < CVT_XB) {
        const size_t per = ((size_t)TOKENS * HDIM / 4) / CVT_XB;
        s4 = (const float4*)xs; d2 = (__half2*)xd;
        i = (size_t)blockIdx.x * per + threadIdx.x; end = (size_t)(blockIdx.x + 1) * per;
    } else {
        const size_t per = ((size_t)EXPERTS * HDIM * FDIM / 4) / CVT_WB;
        s4 = (const float4*)ws; d2 = (__half2*)wd;
        i = (size_t)(blockIdx.x - CVT_XB) * per + threadIdx.x;
        end = (size_t)(blockIdx.x - CVT_XB + 1) * per;
    }
    for (; i < end; i += blockDim.x) {
        float4 v = s4[i];
        d2[2 * i]     = __floats2half2_rn(v.x, v.y);
        d2[2 * i + 1] = __floats2half2_rn(v.z, v.w);
    }
}

// ---------------- PTX helpers ----------------
__device__ __forceinline__ uint32_t smem_u32(const void* p) {
    uint32_t a;
    asm("{ .reg .u64 t; cvta.to.shared.u64 t, %1; cvt.u32.u64 %0, t; }" : "=r"(a) : "l"(p));
    return a;
}
__device__ __forceinline__ void cpa16(uint32_t dst, const void* src) {
    asm volatile("cp.async.cg.shared.global [%0], [%1], 16;" :: "r"(dst), "l"(src));
}
#define CP_COMMIT() asm volatile("cp.async.commit_group;" ::: "memory")
#define CP_WAIT3()  asm volatile("cp.async.wait_group 3;"  ::: "memory")

__device__ __forceinline__ void ldsm_x4(uint32_t* r, uint32_t a) {
    asm volatile("ldmatrix.sync.aligned.m8n8.x4.shared.b16 {%0,%1,%2,%3}, [%4];"
                 : "=r"(r[0]), "=r"(r[1]), "=r"(r[2]), "=r"(r[3]) : "r"(a));
}
__device__ __forceinline__ void ldsm_x4t(uint32_t* r, uint32_t a) {
    asm volatile("ldmatrix.sync.aligned.m8n8.x4.trans.shared.b16 {%0,%1,%2,%3}, [%4];"
                 : "=r"(r[0]), "=r"(r[1]), "=r"(r[2]), "=r"(r[3]) : "r"(a));
}
__device__ __forceinline__ void mma16816(float* c, const uint32_t* a, const uint32_t* b) {
    asm volatile(
        "mma.sync.aligned.m16n8k16.row.col.f32.f16.f16.f32 "
        "{%0,%1,%2,%3}, {%4,%5,%6,%7}, {%8,%9}, {%0,%1,%2,%3};"
        : "+f"(c[0]), "+f"(c[1]), "+f"(c[2]), "+f"(c[3])
        : "r"(a[0]), "r"(a[1]), "r"(a[2]), "r"(a[3]), "r"(b[0]), "r"(b[1]));
}

// HW tanh (sm_75+): single MUFU op instead of the ~12-op library tanhf chain.
__device__ __forceinline__ float tanh_fast(float x) {
    float r; asm("tanh.approx.f32 %0, %1;" : "=f"(r) : "f"(x)); return r;
}
__device__ __forceinline__ float gelu_tanh(float x) {
    float x3 = x * x * x;
    float t  = tanh_fast(0.7978845608028654f * (x + 0.044715f * x3));
    return 0.5f * x * (1.0f + t);
}

// ---------------- SMEM layout ----------------
// BM=128, BN=128, BK=32, 6-stage ring (preload 4, prefetch distance 4).
// A stage: 128 rows x 64B padded to 80B pitch  (5 x 16B, gcd(5,8)=1)  -> 10240 B
// B stage:  32 k-rows x 256B padded to 272B   (17 x 16B, gcd(17,8)=1) ->  8704 B
// 6 stages: 113664 B/CTA; 2 CTAs = 222 KB <= 228 KB SM capacity -> 2 CTAs/SM.
static constexpr int A_PITCH   = 80;
static constexpr int B_PITCH   = 272;
static constexpr int A_STAGE   = 128 * A_PITCH;         // 10240
static constexpr int B_STAGE   = 32 * B_PITCH;          //  8704
static constexpr int NSTAGE    = 6;
static constexpr int B_OFF     = NSTAGE * A_STAGE;      // 61440
static constexpr int SMEM_SIZE = B_OFF + NSTAGE * B_STAGE;  // 113664

// fc1 grid: x = 64 GEMM n-tiles + NX_CVT embedded-cvt columns (R13/R15-proven).
static constexpr int NX_GEMM = FDIM / 128;   // 64
static constexpr int NX_CVT  = 8;            // 8 x 16 x 8 = 1024 cvt blocks
static constexpr int CVT_BLOCKS = NX_CVT * (CAP / 128) * EXPERTS;  // 1024

// ---------------- grouped GEMM: OUT[e] = act(A[e] @ W[e] + bias[e]) ----------------
// CTA 128x128 with 128 threads: 4 warps in 2x2, warp tile 64x64 (R7 shape).
// FC1 grids carry NX_CVT extra x-columns of blocks converting w2 fp32->fp16,
// interleaved through the CTA issue order; fc2 is stream-ordered after fc1.
template <bool FC1>
__global__ void __launch_bounds__(128, 2)
moe_gemm(const float* __restrict__ bias, float* __restrict__ out, int K, int N,
         const float* __restrict__ cvtS, __half* __restrict__ cvtD)
{
    extern __shared__ char smem[];
    const uint32_t sb = smem_u32(smem);
    const int tid  = threadIdx.x;

    if (FC1 && blockIdx.x >= NX_GEMM) {
        // ---- embedded w2 conversion block ----
        const int c = (blockIdx.x - NX_GEMM)
                    + NX_CVT * (blockIdx.y + (CAP / 128) * blockIdx.z); // 0..1023
        const size_t n4_total = (size_t)EXPERTS * FDIM * HDIM / 4;      // 32M float4
        const size_t per_blk  = n4_total / CVT_BLOCKS;                  // 32768
        const float4* s4 = (const float4*)cvtS;
        __half2*      d2 = (__half2*)cvtD;
        size_t base = (size_t)c * per_blk;
        for (size_t j = tid; j < per_blk; j += 128) {
            size_t i = base + j;
            float4 v = s4[i];
            d2[2 * i]     = __floats2half2_rn(v.x, v.y);
            d2[2 * i + 1] = __floats2half2_rn(v.z, v.w);
        }
        return;
    }

    const int wid  = tid >> 5;
    const int lane = tid & 31;

    const int e  = blockIdx.z;
    const int m0 = blockIdx.y * 128;
    const int n0 = blockIdx.x * 128;

    const __half* A = (FC1 ? g_xh  : g_hidh) + ((size_t)(e * CAP + m0)) * (size_t)K;
    const __half* W = (FC1 ? g_w1h : g_w2h) + (size_t)e * K * N + n0;

    const int wm = (wid & 1) * 64;   // warp row offset
    const int wn = (wid >> 1) * 64;  // warp col offset

    // producer mapping (128 threads): A tile 512 segs (4/row), B tile 512 segs
    // (16/row); 4 each per thread.
    auto load_stage = [&](int stage, int kc) {
        uint32_t aS = sb + stage * A_STAGE;
        uint32_t bS = sb + B_OFF + stage * B_STAGE;
        #pragma unroll
        for (int j = 0; j < 4; ++j) {
            const int idx = tid + 128 * j;
            const int row = idx >> 2, seg = idx & 3;
            cpa16(aS + row * A_PITCH + seg * 16,
                  A + (size_t)row * K + kc + seg * 8);
        }
        #pragma unroll
        for (int j = 0; j < 4; ++j) {
            const int idx = tid + 128 * j;
            const int r = idx >> 4, seg = idx & 15;
            cpa16(bS + r * B_PITCH + seg * 16,
                  W + (size_t)(kc + r) * N + seg * 8);
        }
    };

    const int nk = K / 32;
    load_stage(0, 0);  CP_COMMIT();
    load_stage(1, 32); CP_COMMIT();
    load_stage(2, 64); CP_COMMIT();
    load_stage(3, 96); CP_COMMIT();

    float acc[4][8][4];
    #pragma unroll
    for (int i = 0; i < 4; ++i)
        #pragma unroll
        for (int j = 0; j < 8; ++j)
            #pragma unroll
            for (int q = 0; q < 4; ++q) acc[i][j][q] = 0.f;

    const int gid = lane >> 2, tig = lane & 3;
    // A ldmatrix (x4, non-trans)
    const uint32_t a_row  = lane & 15;
    const uint32_t a_koff = (lane >> 4) * 16;
    // B ldmatrix (x4, trans): mats 0,1 -> k 0-7/8-15; mats 2,3 -> +8 cols
    const int bmat  = lane >> 3;
    const int bt_k  = (bmat & 1) * 8 + (lane & 7);
    const int bt_n  = (bmat >> 1) * 8;

    // Hoisted per-warp-invariant LDSM address components: inside the mainloop
    // each address is (stage base) + (precomputed constant), a single IADD.
    uint32_t aOff[4], bOff[4];
    #pragma unroll
    for (int mt = 0; mt < 4; ++mt)
        aOff[mt] = (uint32_t)((wm + mt * 16 + a_row) * A_PITCH) + a_koff;
    #pragma unroll
    for (int nh = 0; nh < 4; ++nh)
        bOff[nh] = (uint32_t)(bt_k * B_PITCH + (wn + nh * 16 + bt_n) * 2);

    // Modulo-free ring cursors: consume slot sc, prefetch slot sp.
    int sc = 0, sp = 4;

    for (int it = 0; it < nk; ++it) {
        // Early prefetch (distance 4): slot (it+4)%6 was last consumed at
        // iter it-2, retired by the barrier of iter it-1 -> race-free; LDG
        // latency gets ~4 iterations of slack before its wait.
        const int pre = it + 4;
        if (pre < nk) {
            load_stage(sp, pre * 32); CP_COMMIT();
            if (++sp == NSTAGE) sp = 0;
        }

        CP_WAIT3();               // <=3 groups pending -> stage `it` complete
        __syncthreads();

        const uint32_t aS = sb + sc * A_STAGE;
        const uint32_t bS = sb + B_OFF + sc * B_STAGE;
        if (++sc == NSTAGE) sc = 0;

        #pragma unroll
        for (int ks = 0; ks < 2; ++ks) {             // two k=16 steps per BK=32
            uint32_t a[4][4], b[4][4];
            #pragma unroll
            for (int mt = 0; mt < 4; ++mt)
                ldsm_x4(a[mt], aS + aOff[mt] + ks * 32);
            #pragma unroll
            for (int nh = 0; nh < 4; ++nh)            // each yields two n8 blocks
                ldsm_x4t(b[nh], bS + bOff[nh] + ks * (16 * B_PITCH));
            #pragma unroll
            for (int mt = 0; mt < 4; ++mt)
                #pragma unroll
                for (int nt = 0; nt < 8; ++nt)
                    mma16816(acc[mt][nt], a[mt], &b[nt >> 1][(nt & 1) * 2]);
        }
    }

    // ---------------- epilogue ----------------
    const float* Bb = bias + (size_t)e * N + n0;
    #pragma unroll
    for (int mt = 0; mt < 4; ++mt) {
        const int r0 = wm + mt * 16 + gid;           // rows r0 and r0+8
        #pragma unroll
        for (int nt = 0; nt < 8; ++nt) {
            const int cl = wn + nt * 8 + 2 * tig;    // cols cl, cl+1
            const float bx = Bb[cl], by = Bb[cl + 1];
            float v00 = acc[mt][nt][0] + bx, v01 = acc[mt][nt][1] + by;
            float v10 = acc[mt][nt][2] + bx, v11 = acc[mt][nt][3] + by;
            size_t base0 = ((size_t)(e * CAP + m0 + r0)) * (size_t)N + n0 + cl;
            if (FC1) {
                v00 = gelu_tanh(v00); v01 = gelu_tanh(v01);
                v10 = gelu_tanh(v10); v11 = gelu_tanh(v11);
                *(__half2*)(g_hidh + base0)                 = __floats2half2_rn(v00, v01);
                *(__half2*)(g_hidh + base0 + (size_t)8 * N) = __floats2half2_rn(v10, v11);
            } else {
                *(float2*)(out + base0)                 = make_float2(v00, v01);
                *(float2*)(out + base0 + (size_t)8 * N) = make_float2(v10, v11);
            }
        }
    }
}

// ---------------- launch (single stream, no events) ----------------
extern "C" void kernel_launch(void* const* d_in, const int* in_sizes, int n_in,
                              void* d_out, int out_size)
{
    const float* x  = (const float*)d_in[0];
    // d_in[1] = tokens_per_expert (equal capacity; unused)
    const float* w1 = (const float*)d_in[2];
    const float* b1 = (const float*)d_in[3];
    const float* w2 = (const float*)d_in[4];
    const float* b2 = (const float*)d_in[5];
    float* out = (float*)d_out;

    cudaFuncSetAttribute(moe_gemm<true>,
                         cudaFuncAttributeMaxDynamicSharedMemorySize, SMEM_SIZE);
    cudaFuncSetAttribute(moe_gemm<false>,
                         cudaFuncAttributeMaxDynamicSharedMemorySize, SMEM_SIZE);

    __half* xh;  cudaGetSymbolAddress((void**)&xh,  g_xh);
    __half* w1h; cudaGetSymbolAddress((void**)&w1h, g_w1h);
    __half* w2h; cudaGetSymbolAddress((void**)&w2h, g_w2h);

    // 1) fp32 -> fp16 staging for x and w1 in ONE launch (w2 converts inside fc1).
    cvt_xw1<<<CVT_XB + CVT_WB, 256>>>(x, xh, w1, w1h);

    // 2) fc1 (+GELU) -> g_hidh, with w2 conversion embedded in extra blocks
    //    (blockIdx.x >= 64), interleaved through the wave schedule.
    moe_gemm<true><<<dim3(NX_GEMM + NX_CVT, CAP / 128, EXPERTS), 128, SMEM_SIZE>>>(
        b1, nullptr, HDIM, FDIM, w2, w2h);

    // 3) fc2 -> out (fp32); w2h guaranteed complete by stream order.
    moe_gemm<false><<<dim3(HDIM / 128, CAP / 128, EXPERTS), 128, SMEM_SIZE>>>(
        b2, out, FDIM, HDIM, nullptr, nullptr);
}